// round 14
// baseline (speedup 1.0000x reference)
#include <cuda_runtime.h>
#include <cstdint>
#include <cstddef>

// ---------------- scratch ----------------
__device__ float    g_H[8192 * 160];        // tanh(xx@W1), tf32-rounded
__device__ unsigned g_W1p[2048 * 160];      // W1 rna-rounded, pair-packed
__device__ unsigned g_W2p[5 * 32 * 2048];   // W2 rna-rounded, pair-packed

__device__ __forceinline__ unsigned f2tf32(float f) {
    unsigned u;
    asm("cvt.rna.tf32.f32 %0, %1;" : "=r"(u) : "f"(f));
    return u;
}

__device__ __forceinline__ void mma_tf32(float c[4], const unsigned a[4],
                                         unsigned b0, unsigned b1) {
    asm volatile(
        "mma.sync.aligned.m16n8k8.row.col.f32.tf32.tf32.f32 "
        "{%0,%1,%2,%3}, {%4,%5,%6,%7}, {%8,%9}, {%0,%1,%2,%3};\n"
        : "+f"(c[0]), "+f"(c[1]), "+f"(c[2]), "+f"(c[3])
        : "r"(a[0]), "r"(a[1]), "r"(a[2]), "r"(a[3]), "r"(b0), "r"(b1));
}

__device__ __forceinline__ void cp16(uint32_t dst, const void* src) {
    asm volatile("cp.async.cg.shared.global [%0], [%1], 16;\n" :: "r"(dst), "l"(src));
}
__device__ __forceinline__ void cp_commit() { asm volatile("cp.async.commit_group;\n"); }
__device__ __forceinline__ void cp_wait0()  { asm volatile("cp.async.wait_group 0;\n" ::: "memory"); }
__device__ __forceinline__ void cp_wait1()  { asm volatile("cp.async.wait_group 1;\n" ::: "memory"); }

__device__ __forceinline__ uint32_t smem_u32(const void* p) {
    return (uint32_t)__cvta_generic_to_shared(p);
}

// ============================================================================
// GEMM1: H[M,160] = tanh( (x + sx*tmx) @ W1[D,160] )
// 256 threads, 8 warps 2(m)x4(n), warp tile 32m x 40n, block 64x160.
// K-step 64, 32 iterations, ONE __syncthreads per iteration, 3-slot rings.
// B from g_W1p (pair-packed, rounded): b0/b1 = one LDS.64.
// ============================================================================
#define G1_AS   34816                    // 2*64*68*4
#define G1_BS   129024                   // 3 * (32 groups * 336 u32 * 4B)
#define G1_XS   53040                    // 3*65*68*4
#define G1_TMX  8192
#define G1_SMEM (G1_AS + G1_BS + G1_XS + G1_TMX)

__global__ void __launch_bounds__(256)
gemm1_kernel(const float* __restrict__ x, const float* __restrict__ state,
             const float* __restrict__ tmx,
             const int* __restrict__ ip, int S, int D, int srows)
{
    extern __shared__ unsigned char sm[];
    unsigned (*As)[64][68] = reinterpret_cast<unsigned (*)[64][68]>(sm);
    unsigned* Bsb          = reinterpret_cast<unsigned*>(sm + G1_AS);        // 3 slots x 10752 u32
    float    (*Xs)[65][68] = reinterpret_cast<float (*)[65][68]>(sm + G1_AS + G1_BS);
    float*    tmxs         = reinterpret_cast<float*>(sm + G1_AS + G1_BS + G1_XS);

    const int tid  = threadIdx.x;
    const int lane = tid & 31;
    const int warp = tid >> 5;
    const int wm   = warp & 1;    // rows wm*32
    const int wn   = warp >> 1;   // cols wn*40
    const int gid  = lane >> 2;
    const int tg   = lane & 3;
    const int m0   = blockIdx.x * 64;
    const int i1   = srows * ip[0] + 1;

    const float* xprow0 = ((m0 % S) == 0)
        ? state + ((size_t)(m0 / S) * srows + i1) * D
        : x + (size_t)(m0 - 1) * D;

    auto issueX1 = [&](int s) {
        int k0 = s * 64, slot = s % 3;
        #pragma unroll
        for (int it = 0; it < 5; it++) {
            int e = tid + it * 256;
            if (e < 1040) {
                int r = e >> 4, cg = (e & 15) * 4;
                const float* src = (r == 0) ? xprow0 + k0 + cg
                                            : x + (size_t)(m0 - 1 + r) * D + k0 + cg;
                cp16(smem_u32(&Xs[slot][r][cg]), src);
            }
        }
    };
    // stage s of packed W1: 2560 float4, src contiguous, dst padded groups
    auto issueB1 = [&](int s) {
        int slot = s % 3;
        const unsigned* src0 = g_W1p + (size_t)s * 10240;
        unsigned* dst0 = Bsb + slot * 10752;
        #pragma unroll
        for (int it = 0; it < 10; it++) {
            int e = tid + it * 256;          // [0,2560)
            int g = e / 80, j = e % 80;      // g = kk*4+tg, j float4 within group
            cp16(smem_u32(dst0 + g * 336 + j * 4), src0 + g * 320 + j * 4);
        }
    };
    auto convertA = [&](int s) {
        int k0 = s * 64, slot = s % 3, buf = s & 1;
        #pragma unroll
        for (int it = 0; it < 4; it++) {
            int e = tid + it * 256;          // [0,1024)
            int r = e >> 4, c4 = (e & 15) * 4;
            float4 xv = *reinterpret_cast<float4*>(&Xs[slot][r + 1][c4]);
            float4 xp = *reinterpret_cast<float4*>(&Xs[slot][r][c4]);
            float4 tv = *reinterpret_cast<float4*>(&tmxs[k0 + c4]);
            uint4 o;
            o.x = f2tf32(xv.x + (xp.x - xv.x) * tv.x);
            o.y = f2tf32(xv.y + (xp.y - xv.y) * tv.y);
            o.z = f2tf32(xv.z + (xp.z - xv.z) * tv.z);
            o.w = f2tf32(xv.w + (xp.w - xv.w) * tv.w);
            *reinterpret_cast<uint4*>(&As[buf][r][c4]) = o;
        }
    };

    #pragma unroll
    for (int it = 0; it < 2; it++) {
        int e = tid + it * 256;
        if (e < D / 4) cp16(smem_u32(tmxs + e * 4), tmx + e * 4);
    }
    issueX1(0); issueB1(0); cp_commit();
    issueX1(1); issueB1(1); cp_commit();

    float acc1[2][5][4];
    #pragma unroll
    for (int a = 0; a < 2; a++)
        #pragma unroll
        for (int b = 0; b < 5; b++)
            #pragma unroll
            for (int c = 0; c < 4; c++) acc1[a][b][c] = 0.f;

    cp_wait1();
    __syncthreads();
    convertA(0);
    __syncthreads();

    const int nkt = D / 64;   // 32
    for (int kt = 0; kt < nkt; kt++) {
        const int buf = kt & 1, slot = kt % 3;

        if (kt + 2 < nkt) { issueX1(kt + 2); issueB1(kt + 2); cp_commit(); }
        if (kt + 1 < nkt) {
            if (kt + 2 < nkt) cp_wait1(); else cp_wait0();
            convertA(kt + 1);
        }

        const unsigned* Bw = Bsb + slot * 10752 + tg * 336;   // tg-stride 336 ≡ 16 mod 32
        #pragma unroll
        for (int kk = 0; kk < 8; kk++) {
            unsigned a[2][4];
            #pragma unroll
            for (int mi = 0; mi < 2; mi++) {
                int ar = wm * 32 + mi * 16 + gid;
                int ac = kk * 8 + tg;
                a[mi][0] = As[buf][ar][ac];
                a[mi][1] = As[buf][ar + 8][ac];
                a[mi][2] = As[buf][ar][ac + 4];
                a[mi][3] = As[buf][ar + 8][ac + 4];
            }
            #pragma unroll
            for (int nt = 0; nt < 5; nt++) {
                int bc = wn * 40 + nt * 8 + gid;
                uint2 b = *reinterpret_cast<const uint2*>(Bw + kk * 1344 + bc * 2);
                mma_tf32(acc1[0][nt], a[0], b.x, b.y);
                mma_tf32(acc1[1][nt], a[1], b.x, b.y);
            }
        }
        __syncthreads();
    }

    #pragma unroll
    for (int mi = 0; mi < 2; mi++)
        #pragma unroll
        for (int nt = 0; nt < 5; nt++) {
            int gc = wn * 40 + nt * 8 + 2 * tg;
            #pragma unroll
            for (int h = 0; h < 2; h++) {
                int gr = m0 + wm * 32 + mi * 16 + gid + h * 8;
                float2 v;
                v.x = __uint_as_float(f2tf32(tanhf(acc1[mi][nt][2 * h])));
                v.y = __uint_as_float(f2tf32(tanhf(acc1[mi][nt][2 * h + 1])));
                *reinterpret_cast<float2*>(g_H + (size_t)gr * 160 + gc) = v;
            }
        }
}

// ============================================================================
// GEMM2 + epilogue. Tile 64m x 64n, 5 modes inner, 3-slot rings, one sync/mode.
// B from g_W2p (pair-packed, rounded): b0/b1 = one LDS.64.
// x/xprev register-hoisted. 73 KB smem -> 3 CTAs/SM.
// ============================================================================
#define G2_HS   27648                    // 3*64*36*4
#define G2_BS   27648                    // 3 * (16 groups * 144 u32 * 4B)
#define G2_XV   17680                    // 65*68*4
#define G2_SMEM (G2_HS + G2_BS + G2_XV)

__global__ void __launch_bounds__(256, 3)
gemm2_kernel(const float* __restrict__ x, const float* __restrict__ state,
             const float* __restrict__ mk, const float* __restrict__ mw,
             const float* __restrict__ mv, const float* __restrict__ mr,
             const float* __restrict__ mg,
             const int* __restrict__ ip, float* __restrict__ out,
             int S, int D, int srows)
{
    extern __shared__ unsigned char sm[];
    unsigned (*Hs)[64][36] = reinterpret_cast<unsigned (*)[64][36]>(sm);
    unsigned* Bsb          = reinterpret_cast<unsigned*>(sm + G2_HS);    // 3 x 2304 u32
    float    (*Xv)[68]     = reinterpret_cast<float (*)[68]>(sm + G2_HS + G2_BS);

    const int tid  = threadIdx.x;
    const int lane = tid & 31;
    const int warp = tid >> 5;
    const int wm   = warp & 1;     // m: wm*32
    const int wn   = warp >> 1;    // n: wn*16
    const int gid  = lane >> 2;
    const int tg   = lane & 3;
    const int n0   = blockIdx.x * 64;
    const int m0   = blockIdx.y * 64;
    const int i1   = srows * ip[0] + 1;

    const float* xprow0 = ((m0 % S) == 0)
        ? state + ((size_t)(m0 / S) * srows + i1) * D
        : x + (size_t)(m0 - 1) * D;

    auto issueH = [&](int f) {
        int slot = f % 3;
        #pragma unroll
        for (int it = 0; it < 2; it++) {
            int e = tid + it * 256;
            int r = e >> 3, c4 = (e & 7) * 4;
            cp16(smem_u32(&Hs[slot][r][c4]),
                 g_H + (size_t)(m0 + r) * 160 + f * 32 + c4);
        }
    };
    // FIXED: full 16 groups x 32 float4 (= 128 u32 data per group)
    auto issueB = [&](int f) {
        int slot = f % 3;
        #pragma unroll
        for (int it = 0; it < 2; it++) {
            int e = tid + it * 256;          // [0,512)
            int g = e >> 5, j = e & 31;      // g = kk*4+tg, j float4 within group
            const unsigned* src = g_W2p + ((size_t)(f * 16 + g) * D + n0) * 2 + j * 4;
            cp16(smem_u32(Bsb + slot * 2304 + g * 144 + j * 4), src);
        }
    };

    #pragma unroll
    for (int it = 0; it < 5; it++) {
        int u = tid + it * 256;
        if (u < 1040) {
            int r = u >> 4, cg = (u & 15) * 4;
            const float* src = (r == 0) ? xprow0 + n0 + cg
                                        : x + (size_t)(m0 - 1 + r) * D + n0 + cg;
            cp16(smem_u32(&Xv[r][cg]), src);
        }
    }
    issueH(0); issueB(0); cp_commit();
    issueH(1); issueB(1); cp_commit();

    cp_wait1();
    __syncthreads();

    float2 rxv[2][2][2], rdx[2][2][2];     // [mi][nt][h], mode-invariant
    #pragma unroll
    for (int mi = 0; mi < 2; mi++)
        #pragma unroll
        for (int nt = 0; nt < 2; nt++) {
            int lc = wn * 16 + nt * 8 + 2 * tg;
            #pragma unroll
            for (int h = 0; h < 2; h++) {
                int lr = wm * 32 + mi * 16 + gid + h * 8;
                float2 xv = *reinterpret_cast<float2*>(&Xv[lr + 1][lc]);
                float2 xp = *reinterpret_cast<float2*>(&Xv[lr][lc]);
                rxv[mi][nt][h] = xv;
                rdx[mi][nt][h].x = xp.x - xv.x;
                rdx[mi][nt][h].y = xp.y - xv.y;
            }
        }

    #pragma unroll
    for (int f = 0; f < 5; f++) {
        const int slot = f % 3;
        if (f > 0) {
            if (f < 4) cp_wait1(); else cp_wait0();
            __syncthreads();
        }
        if (f + 2 <= 4) {
            issueH(f + 2);
            issueB(f + 2);
            cp_commit();
        }

        float acc[2][2][4];
        #pragma unroll
        for (int a = 0; a < 2; a++)
            #pragma unroll
            for (int b = 0; b < 2; b++)
                #pragma unroll
                for (int c = 0; c < 4; c++) acc[a][b][c] = 0.f;

        const unsigned* Bw = Bsb + slot * 2304 + tg * 144;   // tg-stride 144 ≡ 16 mod 32
        #pragma unroll
        for (int kk = 0; kk < 4; kk++) {
            unsigned a[2][4];
            #pragma unroll
            for (int mi = 0; mi < 2; mi++) {
                int ar = wm * 32 + mi * 16 + gid;
                int ac = kk * 8 + tg;
                a[mi][0] = Hs[slot][ar][ac];
                a[mi][1] = Hs[slot][ar + 8][ac];
                a[mi][2] = Hs[slot][ar][ac + 4];
                a[mi][3] = Hs[slot][ar + 8][ac + 4];
            }
            #pragma unroll
            for (int nt = 0; nt < 2; nt++) {
                int bc = wn * 16 + nt * 8 + gid;
                uint2 b = *reinterpret_cast<const uint2*>(Bw + kk * 576 + bc * 2);
                mma_tf32(acc[0][nt], a[0], b.x, b.y);
                mma_tf32(acc[1][nt], a[1], b.x, b.y);
            }
        }

        const float* maa = (f == 0) ? mk : (f == 1) ? mw : (f == 2) ? mv
                         : (f == 3) ? mr : mg;

        #pragma unroll
        for (int nt = 0; nt < 2; nt++) {
            int lc = wn * 16 + nt * 8 + 2 * tg;
            int gc = n0 + lc;
            float2 mm = *reinterpret_cast<const float2*>(maa + gc);
            #pragma unroll
            for (int mi = 0; mi < 2; mi++)
                #pragma unroll
                for (int h = 0; h < 2; h++) {
                    int lr = wm * 32 + mi * 16 + gid + h * 8;
                    float2 xv = rxv[mi][nt][h];
                    float2 dx = rdx[mi][nt][h];
                    float y0 = acc[mi][nt][2 * h];
                    float y1 = acc[mi][nt][2 * h + 1];
                    float2 o;
                    o.x = xv.x + dx.x * (mm.x + y0);
                    o.y = xv.y + dx.y * (mm.y + y1);
                    __stcs(reinterpret_cast<float2*>(
                        out + ((size_t)(m0 + lr) * 5 + f) * D + gc), o);
                }
        }
    }
}

// ---------------------------------------------------------------------------
// prep: rna-round + pair-pack W1 -> g_W1p, W2 -> g_W2p; build new_state.
// ---------------------------------------------------------------------------
__global__ void prep_kernel(const float* __restrict__ w1, const float* __restrict__ w2,
                            const float* __restrict__ x, const float* __restrict__ state,
                            const int* __restrict__ ip, float* __restrict__ outs,
                            int D, int S, int srows, int total, int nb1, int nb2)
{
    int bid = blockIdx.x;
    int tid = threadIdx.x;
    if (bid < nb1) {
        // W1 pack: 32s x 8kk x 4tg x 40 n4 = 40960 items
        int idx = bid * 256 + tid;
        int n4 = idx % 40, g = idx / 40;            // g = (s*8+kk)*4+tg, 0..1023
        int s = g >> 5, rr = g & 31;
        int kk = rr >> 2, tg = rr & 3;
        int row0 = s * 64 + kk * 8 + tg;
        float4 a = *reinterpret_cast<const float4*>(w1 + (size_t)row0 * 160 + n4 * 4);
        float4 b = *reinterpret_cast<const float4*>(w1 + (size_t)(row0 + 4) * 160 + n4 * 4);
        uint4 o0 = { f2tf32(a.x), f2tf32(b.x), f2tf32(a.y), f2tf32(b.y) };
        uint4 o1 = { f2tf32(a.z), f2tf32(b.z), f2tf32(a.w), f2tf32(b.w) };
        unsigned* dst = g_W1p + (size_t)g * 320 + n4 * 8;
        *reinterpret_cast<uint4*>(dst)     = o0;
        *reinterpret_cast<uint4*>(dst + 4) = o1;
    } else if (bid < nb1 + nb2) {
        // W2 pack: 5f x 4kk x 4tg x (D/4) n4 = 80 * D/4 items
        int idx = (bid - nb1) * 256 + tid;
        int nd4 = D / 4;
        int n4 = idx % nd4, g = idx / nd4;          // g = f*16 + kk*4+tg, 0..79
        int f = g >> 4, rr = g & 15;
        int kk = rr >> 2, tg = rr & 3;
        int row0 = f * 32 + kk * 8 + tg;
        float4 a = *reinterpret_cast<const float4*>(w2 + (size_t)row0 * D + n4 * 4);
        float4 b = *reinterpret_cast<const float4*>(w2 + (size_t)(row0 + 4) * D + n4 * 4);
        uint4 o0 = { f2tf32(a.x), f2tf32(b.x), f2tf32(a.y), f2tf32(b.y) };
        uint4 o1 = { f2tf32(a.z), f2tf32(b.z), f2tf32(a.w), f2tf32(b.w) };
        unsigned* dst = g_W2p + (size_t)g * D * 2 + n4 * 8;
        *reinterpret_cast<uint4*>(dst)     = o0;
        *reinterpret_cast<uint4*>(dst + 4) = o1;
    } else {
        int idx = ((bid - nb1 - nb2) * 256 + tid) * 4;
        if (idx < total) {
            int i1 = srows * ip[0] + 1;
            int d = idx % D;
            int r = (idx / D) % srows;
            int b = idx / (D * srows);
            float4 v;
            if (r == i1)
                v = *reinterpret_cast<const float4*>(x + ((size_t)b * S + (S - 1)) * D + d);
            else
                v = *reinterpret_cast<const float4*>(state + idx);
            *reinterpret_cast<float4*>(outs + idx) = v;
        }
    }
}

extern "C" void kernel_launch(void* const* d_in, const int* in_sizes, int n_in,
                              void* d_out, int out_size)
{
    const float* x     = (const float*)d_in[0];
    const float* state = (const float*)d_in[1];
    const float* tmx   = (const float*)d_in[2];
    const float* w1    = (const float*)d_in[3];
    const float* w2    = (const float*)d_in[4];
    const float* mk    = (const float*)d_in[5];
    const float* mw    = (const float*)d_in[6];
    const float* mv    = (const float*)d_in[7];
    const float* mr    = (const float*)d_in[8];
    const float* mg    = (const float*)d_in[9];
    const int*   ip    = (const int*)d_in[10];
    float* out = (float*)d_out;

    const int D     = in_sizes[2];
    const int srows = 2 + D / 32;
    const int Bb    = in_sizes[1] / (srows * D);
    const int M     = in_sizes[0] / D;
    const int S     = M / Bb;

    static bool attr_done = false;
    if (!attr_done) {
        cudaFuncSetAttribute(gemm1_kernel, cudaFuncAttributeMaxDynamicSharedMemorySize, G1_SMEM);
        cudaFuncSetAttribute(gemm2_kernel, cudaFuncAttributeMaxDynamicSharedMemorySize, G2_SMEM);
        attr_done = true;
    }

    long long main_sz = (long long)M * 5 * D;
    long long st_sz   = (long long)Bb * srows * D;
    int total = ((long long)out_size >= main_sz + st_sz) ? (int)st_sz : 0;

    const int nb1 = 40960 / 256;                   // W1 pack blocks
    const int nb2 = (80 * (D / 4)) / 256;          // W2 pack blocks
    const int nb3 = (total / 4 + 255) / 256;
    prep_kernel<<<nb1 + nb2 + nb3, 256>>>(w1, w2, x, state, ip, out + main_sz,
                                          D, S, srows, total, nb1, nb2);
    gemm1_kernel<<<M / 64, 256, G1_SMEM>>>(x, state, tmx, ip, S, D, srows);
    gemm2_kernel<<<dim3(D / 64, M / 64), 256, G2_SMEM>>>(x, state, mk, mw, mv, mr, mg,
                                                         ip, out, S, D, srows);
}